// round 4
// baseline (speedup 1.0000x reference)
#include <cuda_runtime.h>
#include <math.h>

// ---------------- problem constants ----------------
#define D        128
#define NMAX     4096          // max overlap (actual ~2800)
#define LD       4096
#define KTOP     32
#define TAU_INV  10.0f
#define BITW     4096          // 4096*32 bits >= U=100000
#define GT       128           // gemm tile
#define GK       16            // gemm k-chunk
#define NBIN     64            // histogram bins
#define HLO      1.0f          // histogram lower edge (logit units, sim/tau)
#define HW       0.0625f       // bin width  (range [1.0, 5.0])
#define HSCALE   16.0f         // 1/HW
#define BUFC     128           // per-row candidate buffer
#define NJC      8             // j-chunks for hist/collect parallelism
#define CBS      256           // compaction block size
#define CMAXB    128           // max compaction blocks per pair

// ---------------- device scratch ----------------
__device__ float        g_Zw[3][(size_t)NMAX * D];
__device__ float        g_Zs[3][(size_t)NMAX * D];
__device__ float        g_G[3][(size_t)NMAX * NMAX];   // G[p][j*LD+i] = sim_p[i][j]*10
__device__ unsigned int g_hist[3][NMAX][NBIN];
__device__ float        g_theta[3][NMAX];
__device__ int          g_cnt[3][NMAX];
__device__ int          g_flag[3][NMAX];
__device__ float        g_buf[3][NMAX][BUFC];
__device__ float        g_rowloss[3][NMAX];
__device__ float        g_pair[3];
__device__ unsigned int g_bitmap[2][BITW];              // 0: cart, 1: purchase
__device__ int          g_common[3][NMAX];
__device__ int          g_bcnt[3][CMAXB];
__device__ int          g_boff[3][CMAXB];
__device__ int          g_N[3];
__device__ int          g_is64;

// ---------------- f32x2 helpers ----------------
typedef unsigned long long ull;
__device__ __forceinline__ ull pack2(float x, float y) {
    ull r; asm("mov.b64 %0,{%1,%2};" : "=l"(r) : "f"(x), "f"(y)); return r;
}
__device__ __forceinline__ void ffma2(ull& c, ull a, ull b) {
    asm("fma.rn.f32x2 %0,%1,%2,%0;" : "+l"(c) : "l"(a), "l"(b));
}

// ---------------- int64 vs int32 detection ----------------
__global__ void k_detect(const int* __restrict__ u, int n) {
    __shared__ int nz;
    if (threadIdx.x == 0) nz = 0;
    __syncthreads();
    int limit = n < 128 ? n : 128;
    for (int i = 1 + 2 * (int)threadIdx.x; i < limit; i += 2 * (int)blockDim.x)
        if (u[i] != 0) atomicAdd(&nz, 1);
    __syncthreads();
    if (threadIdx.x == 0) g_is64 = (nz == 0) ? 1 : 0;
}
__device__ __forceinline__ int get_user(const void* p, int i) {
    return g_is64 ? (int)((const long long*)p)[i] : ((const int*)p)[i];
}
__device__ __forceinline__ int in_set(int bm, int v) {
    unsigned uv = (unsigned)v;
    return (uv < BITW * 32u) && ((g_bitmap[bm][uv >> 5] >> (uv & 31)) & 1u);
}

// ---------------- zero scratch ----------------
__global__ void k_zero() {
    int t = blockIdx.x * blockDim.x + threadIdx.x;
    int stride = gridDim.x * blockDim.x;
    for (int i = t; i < 2 * BITW; i += stride) ((unsigned*)g_bitmap)[i] = 0u;
    for (int i = t; i < 3 * NMAX * NBIN; i += stride) ((unsigned*)g_hist)[i] = 0u;
    for (int i = t; i < 3 * NMAX; i += stride) { ((int*)g_cnt)[i] = 0; ((int*)g_flag)[i] = 0; }
    if (t < 3) g_N[t] = 0;
}

__global__ void k_build(const void* __restrict__ uc, int nc,
                        const void* __restrict__ up, int npv) {
    int i = blockIdx.x * blockDim.x + threadIdx.x;
    if (i < nc) {
        unsigned v = (unsigned)get_user(uc, i);
        if (v < BITW * 32u) atomicOr(&g_bitmap[0][v >> 5], 1u << (v & 31));
    }
    if (i < npv) {
        unsigned v = (unsigned)get_user(up, i);
        if (v < BITW * 32u) atomicOr(&g_bitmap[1][v >> 5], 1u << (v & 31));
    }
}

// ---------------- 3-phase stable compaction ----------------
__device__ __forceinline__ void pair_src(int p, const void* uw0, int n0,
                                         const void* uw1, int n1,
                                         const void* uw2, int n2,
                                         const void*& uw, int& nw, int& bm) {
    uw = p == 0 ? uw0 : (p == 1 ? uw1 : uw2);
    nw = p == 0 ? n0  : (p == 1 ? n1  : n2);
    bm = p == 0 ? 0 : 1;
}

__global__ void __launch_bounds__(CBS)
k_ccount(const void* uw0, int n0, const void* uw1, int n1,
         const void* uw2, int n2) {
    __shared__ int ws[CBS / 32];
    int p = blockIdx.y;
    const void* uw; int nw, bm;
    pair_src(p, uw0, n0, uw1, n1, uw2, n2, uw, nw, bm);
    int i = blockIdx.x * CBS + threadIdx.x;
    int flag = (i < nw) ? in_set(bm, get_user(uw, i)) : 0;
    unsigned b = __ballot_sync(0xffffffffu, flag);
    int lane = threadIdx.x & 31, wid = threadIdx.x >> 5;
    if (lane == 0) ws[wid] = __popc(b);
    __syncthreads();
    if (threadIdx.x == 0) {
        int s = 0;
        #pragma unroll
        for (int w = 0; w < CBS / 32; w++) s += ws[w];
        g_bcnt[p][blockIdx.x] = s;
    }
}

__global__ void k_cscan(int nblk) {
    int p = threadIdx.x;      // 3 threads
    if (p >= 3) return;
    int acc = 0;
    for (int b = 0; b < nblk; b++) {
        g_boff[p][b] = acc;
        acc += g_bcnt[p][b];
    }
    g_N[p] = acc > NMAX ? NMAX : acc;
}

__global__ void __launch_bounds__(CBS)
k_cwrite(const void* uw0, int n0, const void* uw1, int n1,
         const void* uw2, int n2) {
    __shared__ int ws[CBS / 32];
    __shared__ int wo[CBS / 32];
    int p = blockIdx.y;
    const void* uw; int nw, bm;
    pair_src(p, uw0, n0, uw1, n1, uw2, n2, uw, nw, bm);
    int i = blockIdx.x * CBS + threadIdx.x;
    int v = 0, flag = 0;
    if (i < nw) { v = get_user(uw, i); flag = in_set(bm, v); }
    unsigned b = __ballot_sync(0xffffffffu, flag);
    int lane = threadIdx.x & 31, wid = threadIdx.x >> 5;
    int wp = __popc(b & ((1u << lane) - 1));
    if (lane == 0) ws[wid] = __popc(b);
    __syncthreads();
    if (threadIdx.x == 0) {
        int s = 0;
        #pragma unroll
        for (int w = 0; w < CBS / 32; w++) { wo[w] = s; s += ws[w]; }
    }
    __syncthreads();
    int pos = g_boff[p][blockIdx.x] + wo[wid] + wp;
    if (flag && pos < NMAX) g_common[p][pos] = v;
}

// ---------------- gather + L2 normalize ----------------
__global__ void __launch_bounds__(256)
k_gather(const float* ev, const float* ec, const float* ep) {
    int p = blockIdx.y;
    const float* ew = p == 0 ? ev : (p == 1 ? ec : ev);
    const float* es = p == 0 ? ec : ep;
    int N = g_N[p];
    int lane = threadIdx.x & 31;
    int row  = blockIdx.x * 8 + (threadIdx.x >> 5);
    if (row >= N) return;
    int u = g_common[p][row];
    {
        float4 a = ((const float4*)(ew + (size_t)u * D))[lane];
        float ss = a.x * a.x + a.y * a.y + a.z * a.z + a.w * a.w;
        #pragma unroll
        for (int o = 16; o; o >>= 1) ss += __shfl_xor_sync(0xffffffffu, ss, o);
        float inv = 1.0f / fmaxf(sqrtf(ss), 1e-12f);
        ((float4*)(g_Zw[p] + (size_t)row * D))[lane] =
            make_float4(a.x * inv, a.y * inv, a.z * inv, a.w * inv);
    }
    {
        float4 a = ((const float4*)(es + (size_t)u * D))[lane];
        float ss = a.x * a.x + a.y * a.y + a.z * a.z + a.w * a.w;
        #pragma unroll
        for (int o = 16; o; o >>= 1) ss += __shfl_xor_sync(0xffffffffu, ss, o);
        float inv = 1.0f / fmaxf(sqrtf(ss), 1e-12f);
        ((float4*)(g_Zs[p] + (size_t)row * D))[lane] =
            make_float4(a.x * inv, a.y * inv, a.z * inv, a.w * inv);
    }
}

// ---------------- persistent FFMA2 GEMM ----------------
__global__ void __launch_bounds__(256) k_gemm() {
    __shared__ __align__(16) float As[GK][GT + 4];
    __shared__ __align__(16) float Bs[GK][GT + 4];

    int nb0 = (g_N[0] + GT - 1) >> 7, nt0 = nb0 * nb0;
    int nb1 = (g_N[1] + GT - 1) >> 7, nt1 = nb1 * nb1;
    int nb2 = (g_N[2] + GT - 1) >> 7, nt2 = nb2 * nb2;
    int total = nt0 + nt1 + nt2;

    int tid = threadIdx.x;
    int tx = tid & 15, ty = tid >> 4;

    for (int t = blockIdx.x; t < total; t += gridDim.x) {
        int p, tt, nb;
        if (t < nt0)            { p = 0; tt = t;             nb = nb0; }
        else if (t < nt0 + nt1) { p = 1; tt = t - nt0;       nb = nb1; }
        else                    { p = 2; tt = t - nt0 - nt1; nb = nb2; }
        const float* Zw = g_Zw[p];
        const float* Zs = g_Zs[p];
        float*       G  = g_G[p];
        int j0 = (tt / nb) << 7;
        int i0 = (tt % nb) << 7;

        ull c[8][4];
        #pragma unroll
        for (int a = 0; a < 8; a++)
            #pragma unroll
            for (int b = 0; b < 4; b++) c[a][b] = 0ull;

        for (int k0 = 0; k0 < D; k0 += GK) {
            __syncthreads();
            #pragma unroll
            for (int q = tid; q < 512; q += 256) {
                int row = q >> 2, c4 = q & 3;
                float4 a = ((const float4*)(Zw + (size_t)(j0 + row) * D + k0))[c4];
                As[c4 * 4 + 0][row] = a.x; As[c4 * 4 + 1][row] = a.y;
                As[c4 * 4 + 2][row] = a.z; As[c4 * 4 + 3][row] = a.w;
                float4 b = ((const float4*)(Zs + (size_t)(i0 + row) * D + k0))[c4];
                Bs[c4 * 4 + 0][row] = b.x; Bs[c4 * 4 + 1][row] = b.y;
                Bs[c4 * 4 + 2][row] = b.z; Bs[c4 * 4 + 3][row] = b.w;
            }
            __syncthreads();
            #pragma unroll
            for (int k = 0; k < GK; k++) {
                float4 a0 = *(const float4*)&As[k][ty * 8];
                float4 a1 = *(const float4*)&As[k][ty * 8 + 4];
                float4 b0 = *(const float4*)&Bs[k][tx * 8];
                float4 b1 = *(const float4*)&Bs[k][tx * 8 + 4];
                ull B[4] = { pack2(b0.x, b0.y), pack2(b0.z, b0.w),
                             pack2(b1.x, b1.y), pack2(b1.z, b1.w) };
                float av[8] = { a0.x, a0.y, a0.z, a0.w, a1.x, a1.y, a1.z, a1.w };
                #pragma unroll
                for (int jj = 0; jj < 8; jj++) {
                    ull aa = pack2(av[jj], av[jj]);
                    #pragma unroll
                    for (int ii = 0; ii < 4; ii++) ffma2(c[jj][ii], aa, B[ii]);
                }
            }
        }
        #pragma unroll
        for (int jj = 0; jj < 8; jj++) {
            float2* rowp = (float2*)(G + (size_t)(j0 + ty * 8 + jj) * LD + i0 + tx * 8);
            #pragma unroll
            for (int ii = 0; ii < 4; ii++) {
                float2 v = *(float2*)&c[jj][ii];
                v.x *= TAU_INV; v.y *= TAU_INV;
                rowp[ii] = v;
            }
        }
    }
}

// ---------------- histogram pass (tail only, global atomics) ----------------
__global__ void __launch_bounds__(256) k_hist() {
    int p = blockIdx.z;
    int N = g_N[p];
    int i = blockIdx.x * 256 + threadIdx.x;
    if (i >= N) return;
    int c = blockIdx.y;
    int len = (N + NJC - 1) / NJC;
    int j0 = c * len, j1 = j0 + len; if (j1 > N) j1 = N;
    const float* G = g_G[p];
    unsigned* H = g_hist[p][i];

    int j = j0;
    for (; j + 4 <= j1; j += 4) {
        float v0 = G[(size_t)(j + 0) * LD + i];
        float v1 = G[(size_t)(j + 1) * LD + i];
        float v2 = G[(size_t)(j + 2) * LD + i];
        float v3 = G[(size_t)(j + 3) * LD + i];
        if (j + 0 != i && v0 > HLO) { int b = (int)((v0 - HLO) * HSCALE); atomicAdd(&H[b < NBIN ? b : NBIN - 1], 1u); }
        if (j + 1 != i && v1 > HLO) { int b = (int)((v1 - HLO) * HSCALE); atomicAdd(&H[b < NBIN ? b : NBIN - 1], 1u); }
        if (j + 2 != i && v2 > HLO) { int b = (int)((v2 - HLO) * HSCALE); atomicAdd(&H[b < NBIN ? b : NBIN - 1], 1u); }
        if (j + 3 != i && v3 > HLO) { int b = (int)((v3 - HLO) * HSCALE); atomicAdd(&H[b < NBIN ? b : NBIN - 1], 1u); }
    }
    for (; j < j1; j++) {
        float v = G[(size_t)j * LD + i];
        if (j != i && v > HLO) { int b = (int)((v - HLO) * HSCALE); atomicAdd(&H[b < NBIN ? b : NBIN - 1], 1u); }
    }
}

// ---------------- per-row threshold from histogram ----------------
__global__ void __launch_bounds__(256) k_theta() {
    int p = blockIdx.y;
    int N = g_N[p];
    int i = blockIdx.x * 256 + threadIdx.x;
    if (i >= N) return;
    const unsigned* H = g_hist[p][i];
    unsigned acc = 0;
    float th = -1e30f;   // fewer than KTOP above HLO -> collect everything
    #pragma unroll
    for (int b = NBIN - 1; b >= 0; b--) {
        acc += H[b];
        if (acc >= KTOP) { th = HLO + (float)b * HW - 1e-3f; break; }
    }
    g_theta[p][i] = th;
}

// ---------------- collect values >= theta ----------------
__global__ void __launch_bounds__(256) k_collect() {
    int p = blockIdx.z;
    int N = g_N[p];
    int i = blockIdx.x * 256 + threadIdx.x;
    if (i >= N) return;
    int c = blockIdx.y;
    int len = (N + NJC - 1) / NJC;
    int j0 = c * len, j1 = j0 + len; if (j1 > N) j1 = N;
    const float* G = g_G[p];
    float th = g_theta[p][i];
    float* buf = g_buf[p][i];

    int j = j0;
    for (; j + 4 <= j1; j += 4) {
        #pragma unroll
        for (int u = 0; u < 4; u++) {
            float v = G[(size_t)(j + u) * LD + i];
            if (j + u != i && v >= th) {
                int pos = atomicAdd(&g_cnt[p][i], 1);
                if (pos < BUFC) buf[pos] = v; else g_flag[p][i] = 1;
            }
        }
    }
    for (; j < j1; j++) {
        float v = G[(size_t)j * LD + i];
        if (j != i && v >= th) {
            int pos = atomicAdd(&g_cnt[p][i], 1);
            if (pos < BUFC) buf[pos] = v; else g_flag[p][i] = 1;
        }
    }
}

// ---------------- sorted-descending register insert ----------------
#define TK_INSERT(T, v)                                   \
    do { float _v = (v);                                  \
        _Pragma("unroll")                                 \
        for (int _k = 0; _k < KTOP; _k++) {               \
            float _t = T[_k];                             \
            T[_k] = fmaxf(_t, _v);                        \
            _v = fminf(_t, _v);                           \
        }                                                 \
    } while (0)

// ---------------- select exact top-32 from buffer + LSE ----------------
__global__ void __launch_bounds__(256) k_select() {
    int p = blockIdx.y;
    int N = g_N[p];
    int i = blockIdx.x * 256 + threadIdx.x;
    if (i >= N) return;
    if (g_flag[p][i]) return;            // fallback kernel handles
    int cnt = g_cnt[p][i]; if (cnt > BUFC) cnt = BUFC;
    const float* buf = g_buf[p][i];
    float T[KTOP];
    #pragma unroll
    for (int k = 0; k < KTOP; k++) T[k] = -INFINITY;
    for (int q = 0; q < cnt; q++) {
        float v = buf[q];
        if (v > T[KTOP - 1]) TK_INSERT(T, v);
    }
    float pos = g_G[p][(size_t)i * LD + i];
    float m = fmaxf(pos, T[0]);
    float s = expf(pos - m);
    #pragma unroll
    for (int k = 0; k < KTOP; k++) s += expf(T[k] - m);
    g_rowloss[p][i] = m + logf(s) - pos;
}

// ---------------- fallback: exact full-row scan (rare/never) ----------------
__global__ void __launch_bounds__(256) k_fallback() {
    int p = blockIdx.y;
    int N = g_N[p];
    int i = blockIdx.x * 256 + threadIdx.x;
    if (i >= N) return;
    if (!g_flag[p][i]) return;
    const float* G = g_G[p];
    float T[KTOP];
    #pragma unroll
    for (int k = 0; k < KTOP; k++) T[k] = -INFINITY;
    for (int j = 0; j < N; j++) {
        float v = G[(size_t)j * LD + i];
        if (j != i && v > T[KTOP - 1]) TK_INSERT(T, v);
    }
    float pos = G[(size_t)i * LD + i];
    float m = fmaxf(pos, T[0]);
    float s = expf(pos - m);
    #pragma unroll
    for (int k = 0; k < KTOP; k++) s += expf(T[k] - m);
    g_rowloss[p][i] = m + logf(s) - pos;
}

// ---------------- deterministic reduction ----------------
__global__ void __launch_bounds__(1024) k_reduce() {
    __shared__ float s[1024];
    int p = blockIdx.x;
    int N = g_N[p];
    int t = threadIdx.x;
    float acc = 0.0f;
    for (int i = t; i < N; i += 1024) acc += g_rowloss[p][i];
    s[t] = acc;
    __syncthreads();
    for (int o = 512; o; o >>= 1) {
        if (t < o) s[t] += s[t + o];
        __syncthreads();
    }
    if (t == 0) g_pair[p] = (N >= 4) ? s[0] / (float)N : 0.0f;
}

__global__ void k_final(float* __restrict__ out) {
    out[0] = 0.2f * g_pair[0] + 1.0f * g_pair[1] + 1.0f * g_pair[2];
}

// ---------------- launch ----------------
extern "C" void kernel_launch(void* const* d_in, const int* in_sizes, int n_in,
                              void* d_out, int out_size) {
    const float* ev = (const float*)d_in[0];
    const float* ec = (const float*)d_in[1];
    const float* ep = (const float*)d_in[2];
    const void*  uv = d_in[3]; int nv  = in_sizes[3];
    const void*  uc = d_in[4]; int nc  = in_sizes[4];
    const void*  up = d_in[5]; int np_ = in_sizes[5];

    int nwmax = nv > nc ? nv : nc; if (np_ > nwmax) nwmax = np_;
    int nblk = (nwmax + CBS - 1) / CBS; if (nblk > CMAXB) nblk = CMAXB;

    k_detect<<<1, 64>>>((const int*)uv, nv);
    k_zero<<<148, 256>>>();
    k_build<<<(nwmax + 255) / 256, 256>>>(uc, nc, up, np_);
    // pairs: (view->cart), (cart->purchase), (view->purchase)
    k_ccount<<<dim3(nblk, 3), CBS>>>(uv, nv, uc, nc, uv, nv);
    k_cscan<<<1, 32>>>(nblk);
    k_cwrite<<<dim3(nblk, 3), CBS>>>(uv, nv, uc, nc, uv, nv);
    k_gather<<<dim3(NMAX / 8, 3), 256>>>(ev, ec, ep);
    k_gemm<<<296, 256>>>();
    k_hist<<<dim3(NMAX / 256, NJC, 3), 256>>>();
    k_theta<<<dim3(NMAX / 256, 3), 256>>>();
    k_collect<<<dim3(NMAX / 256, NJC, 3), 256>>>();
    k_select<<<dim3(NMAX / 256, 3), 256>>>();
    k_fallback<<<dim3(NMAX / 256, 3), 256>>>();
    k_reduce<<<3, 1024>>>();
    k_final<<<1, 1>>>((float*)d_out);
}

// round 6
// speedup vs baseline: 1.7622x; 1.7622x over previous
#include <cuda_runtime.h>
#include <math.h>

// ---------------- problem constants ----------------
#define D        128
#define NMAX     4096          // max overlap (actual ~2800)
#define KTOP     32
#define TAU_INV  10.0f
#define BITW     4096          // 4096*32 bits >= U=100000
#define GT       128           // gemm tile
#define GK       16            // gemm k-chunk
#define BUFC     160           // per-row candidate buffer capacity
#define C0       80.0f         // target expected candidates per row
#define CBS      256           // compaction block size
#define CMAXB    128           // max compaction blocks per pair

// ---------------- device scratch ----------------
__device__ float        g_Zw[3][(size_t)NMAX * D];   // static zero; rows >= N stay 0
__device__ float        g_Zs[3][(size_t)NMAX * D];
__device__ float        g_buf[3][NMAX][BUFC];
__device__ float        g_pos[3][NMAX];
__device__ int          g_cnt[3][NMAX];
__device__ int          g_flag[3][NMAX];
__device__ float        g_rowloss[3][NMAX];
__device__ float        g_pair[3];
__device__ float        g_thp[3];
__device__ unsigned int g_bitmap[2][BITW];           // 0: cart, 1: purchase
__device__ int          g_common[3][NMAX];
__device__ int          g_bcnt[3][CMAXB];
__device__ int          g_boff[3][CMAXB];
__device__ int          g_N[3];
__device__ int          g_is64;

// ---------------- f32x2 helpers ----------------
typedef unsigned long long ull;
__device__ __forceinline__ ull pack2(float x, float y) {
    ull r; asm("mov.b64 %0,{%1,%2};" : "=l"(r) : "f"(x), "f"(y)); return r;
}
__device__ __forceinline__ void ffma2(ull& c, ull a, ull b) {
    asm("fma.rn.f32x2 %0,%1,%2,%0;" : "+l"(c) : "l"(a), "l"(b));
}

// ---------------- int64 vs int32 detection ----------------
__global__ void k_detect(const int* __restrict__ u, int n) {
    __shared__ int nz;
    if (threadIdx.x == 0) nz = 0;
    __syncthreads();
    int limit = n < 128 ? n : 128;
    for (int i = 1 + 2 * (int)threadIdx.x; i < limit; i += 2 * (int)blockDim.x)
        if (u[i] != 0) atomicAdd(&nz, 1);
    __syncthreads();
    if (threadIdx.x == 0) g_is64 = (nz == 0) ? 1 : 0;
}
__device__ __forceinline__ int get_user(const void* p, int i) {
    return g_is64 ? (int)((const long long*)p)[i] : ((const int*)p)[i];
}
__device__ __forceinline__ int in_set(int bm, int v) {
    unsigned uv = (unsigned)v;
    return (uv < BITW * 32u) && ((g_bitmap[bm][uv >> 5] >> (uv & 31)) & 1u);
}

// ---------------- zero scratch (small: ~130KB) ----------------
__global__ void k_zero() {
    int t = blockIdx.x * blockDim.x + threadIdx.x;
    int stride = gridDim.x * blockDim.x;
    for (int i = t; i < 2 * BITW; i += stride) ((unsigned*)g_bitmap)[i] = 0u;
    for (int i = t; i < 3 * NMAX; i += stride) { ((int*)g_cnt)[i] = 0; ((int*)g_flag)[i] = 0; }
    if (t < 3) g_N[t] = 0;
}

__global__ void k_build(const void* __restrict__ uc, int nc,
                        const void* __restrict__ up, int npv) {
    int i = blockIdx.x * blockDim.x + threadIdx.x;
    if (i < nc) {
        unsigned v = (unsigned)get_user(uc, i);
        if (v < BITW * 32u) atomicOr(&g_bitmap[0][v >> 5], 1u << (v & 31));
    }
    if (i < npv) {
        unsigned v = (unsigned)get_user(up, i);
        if (v < BITW * 32u) atomicOr(&g_bitmap[1][v >> 5], 1u << (v & 31));
    }
}

// ---------------- 3-phase stable compaction ----------------
__device__ __forceinline__ void pair_src(int p, const void* uw0, int n0,
                                         const void* uw1, int n1,
                                         const void* uw2, int n2,
                                         const void*& uw, int& nw, int& bm) {
    uw = p == 0 ? uw0 : (p == 1 ? uw1 : uw2);
    nw = p == 0 ? n0  : (p == 1 ? n1  : n2);
    bm = p == 0 ? 0 : 1;
}

__global__ void __launch_bounds__(CBS)
k_ccount(const void* uw0, int n0, const void* uw1, int n1,
         const void* uw2, int n2) {
    __shared__ int ws[CBS / 32];
    int p = blockIdx.y;
    const void* uw; int nw, bm;
    pair_src(p, uw0, n0, uw1, n1, uw2, n2, uw, nw, bm);
    int i = blockIdx.x * CBS + threadIdx.x;
    int flag = (i < nw) ? in_set(bm, get_user(uw, i)) : 0;
    unsigned b = __ballot_sync(0xffffffffu, flag);
    int lane = threadIdx.x & 31, wid = threadIdx.x >> 5;
    if (lane == 0) ws[wid] = __popc(b);
    __syncthreads();
    if (threadIdx.x == 0) {
        int s = 0;
        #pragma unroll
        for (int w = 0; w < CBS / 32; w++) s += ws[w];
        g_bcnt[p][blockIdx.x] = s;
    }
}

// scan block counts + set N + compute per-pair collect threshold
__global__ void k_cscan(int nblk) {
    int p = threadIdx.x;
    if (p >= 3) return;
    int acc = 0;
    for (int b = 0; b < nblk; b++) { g_boff[p][b] = acc; acc += g_bcnt[p][b]; }
    int N = acc > NMAX ? NMAX : acc;
    g_N[p] = N;
    float th = -1e30f;                         // N small: collect all negatives
    if (N > BUFC) {
        float sigma = TAU_INV / sqrtf((float)D);   // sim/tau std for unit vectors
        th = sigma * 1.4142136f * erfinvf(1.0f - (2.0f * C0) / (float)N);
    }
    g_thp[p] = th;
}

__global__ void __launch_bounds__(CBS)
k_cwrite(const void* uw0, int n0, const void* uw1, int n1,
         const void* uw2, int n2) {
    __shared__ int ws[CBS / 32];
    __shared__ int wo[CBS / 32];
    int p = blockIdx.y;
    const void* uw; int nw, bm;
    pair_src(p, uw0, n0, uw1, n1, uw2, n2, uw, nw, bm);
    int i = blockIdx.x * CBS + threadIdx.x;
    int v = 0, flag = 0;
    if (i < nw) { v = get_user(uw, i); flag = in_set(bm, v); }
    unsigned b = __ballot_sync(0xffffffffu, flag);
    int lane = threadIdx.x & 31, wid = threadIdx.x >> 5;
    int wp = __popc(b & ((1u << lane) - 1));
    if (lane == 0) ws[wid] = __popc(b);
    __syncthreads();
    if (threadIdx.x == 0) {
        int s = 0;
        #pragma unroll
        for (int w = 0; w < CBS / 32; w++) { wo[w] = s; s += ws[w]; }
    }
    __syncthreads();
    int pos = g_boff[p][blockIdx.x] + wo[wid] + wp;
    if (flag && pos < NMAX) g_common[p][pos] = v;
}

// ---------------- gather + L2 normalize ----------------
__global__ void __launch_bounds__(256)
k_gather(const float* ev, const float* ec, const float* ep) {
    int p = blockIdx.y;
    const float* ew = p == 0 ? ev : (p == 1 ? ec : ev);
    const float* es = p == 0 ? ec : ep;
    int N = g_N[p];
    int lane = threadIdx.x & 31;
    int row  = blockIdx.x * 8 + (threadIdx.x >> 5);
    if (row >= N) return;
    int u = g_common[p][row];
    {
        float4 a = ((const float4*)(ew + (size_t)u * D))[lane];
        float ss = a.x * a.x + a.y * a.y + a.z * a.z + a.w * a.w;
        #pragma unroll
        for (int o = 16; o; o >>= 1) ss += __shfl_xor_sync(0xffffffffu, ss, o);
        float inv = 1.0f / fmaxf(sqrtf(ss), 1e-12f);
        ((float4*)(g_Zw[p] + (size_t)row * D))[lane] =
            make_float4(a.x * inv, a.y * inv, a.z * inv, a.w * inv);
    }
    {
        float4 a = ((const float4*)(es + (size_t)u * D))[lane];
        float ss = a.x * a.x + a.y * a.y + a.z * a.z + a.w * a.w;
        #pragma unroll
        for (int o = 16; o; o >>= 1) ss += __shfl_xor_sync(0xffffffffu, ss, o);
        float inv = 1.0f / fmaxf(sqrtf(ss), 1e-12f);
        ((float4*)(g_Zs[p] + (size_t)row * D))[lane] =
            make_float4(a.x * inv, a.y * inv, a.z * inv, a.w * inv);
    }
}

// ---------------- persistent FFMA2 GEMM with fused candidate collection ----
// sim[i][j]*10 = 10*dot(Zs[i], Zw[j]).  No G matrix is materialized: the
// epilogue appends values >= theta to per-row buffers and captures the diag.
__global__ void __launch_bounds__(256) k_gemm() {
    __shared__ __align__(16) float As[GK][GT + 4];
    __shared__ __align__(16) float Bs[GK][GT + 4];

    int nb0 = (g_N[0] + GT - 1) >> 7, nt0 = nb0 * nb0;
    int nb1 = (g_N[1] + GT - 1) >> 7, nt1 = nb1 * nb1;
    int nb2 = (g_N[2] + GT - 1) >> 7, nt2 = nb2 * nb2;
    int total = nt0 + nt1 + nt2;

    int tid = threadIdx.x;
    int tx = tid & 15, ty = tid >> 4;

    for (int t = blockIdx.x; t < total; t += gridDim.x) {
        int p, tt, nb;
        if (t < nt0)            { p = 0; tt = t;             nb = nb0; }
        else if (t < nt0 + nt1) { p = 1; tt = t - nt0;       nb = nb1; }
        else                    { p = 2; tt = t - nt0 - nt1; nb = nb2; }
        int N = g_N[p];
        const float* Zw = g_Zw[p];
        const float* Zs = g_Zs[p];
        int j0 = (tt / nb) << 7;
        int i0 = (tt % nb) << 7;

        ull c[8][4];
        #pragma unroll
        for (int a = 0; a < 8; a++)
            #pragma unroll
            for (int b = 0; b < 4; b++) c[a][b] = 0ull;

        for (int k0 = 0; k0 < D; k0 += GK) {
            __syncthreads();
            #pragma unroll
            for (int q = tid; q < 512; q += 256) {
                int row = q >> 2, c4 = q & 3;
                float4 a = ((const float4*)(Zw + (size_t)(j0 + row) * D + k0))[c4];
                As[c4 * 4 + 0][row] = a.x; As[c4 * 4 + 1][row] = a.y;
                As[c4 * 4 + 2][row] = a.z; As[c4 * 4 + 3][row] = a.w;
                float4 b = ((const float4*)(Zs + (size_t)(i0 + row) * D + k0))[c4];
                Bs[c4 * 4 + 0][row] = b.x; Bs[c4 * 4 + 1][row] = b.y;
                Bs[c4 * 4 + 2][row] = b.z; Bs[c4 * 4 + 3][row] = b.w;
            }
            __syncthreads();
            #pragma unroll
            for (int k = 0; k < GK; k++) {
                float4 a0 = *(const float4*)&As[k][ty * 8];
                float4 a1 = *(const float4*)&As[k][ty * 8 + 4];
                float4 b0 = *(const float4*)&Bs[k][tx * 8];
                float4 b1 = *(const float4*)&Bs[k][tx * 8 + 4];
                ull B[4] = { pack2(b0.x, b0.y), pack2(b0.z, b0.w),
                             pack2(b1.x, b1.y), pack2(b1.z, b1.w) };
                float av[8] = { a0.x, a0.y, a0.z, a0.w, a1.x, a1.y, a1.z, a1.w };
                #pragma unroll
                for (int jj = 0; jj < 8; jj++) {
                    ull aa = pack2(av[jj], av[jj]);
                    #pragma unroll
                    for (int ii = 0; ii < 4; ii++) ffma2(c[jj][ii], aa, B[ii]);
                }
            }
        }

        // ---- fused epilogue: threshold-collect + diagonal capture ----
        float th = g_thp[p];
        #pragma unroll
        for (int jj = 0; jj < 8; jj++) {
            int jg = j0 + ty * 8 + jj;
            if (jg >= N) continue;
            #pragma unroll
            for (int ii = 0; ii < 4; ii++) {
                float2 v = *(float2*)&c[jj][ii];
                v.x *= TAU_INV; v.y *= TAU_INV;
                int ig = i0 + tx * 8 + ii * 2;
                if (ig < N) {
                    if (jg == ig) g_pos[p][ig] = v.x;
                    else if (v.x >= th) {
                        int q = atomicAdd(&g_cnt[p][ig], 1);
                        if (q < BUFC) g_buf[p][ig][q] = v.x; else g_flag[p][ig] = 1;
                    }
                }
                if (ig + 1 < N) {
                    if (jg == ig + 1) g_pos[p][ig + 1] = v.y;
                    else if (v.y >= th) {
                        int q = atomicAdd(&g_cnt[p][ig + 1], 1);
                        if (q < BUFC) g_buf[p][ig + 1][q] = v.y; else g_flag[p][ig + 1] = 1;
                    }
                }
            }
        }
    }
}

// ---------------- sorted-descending register insert ----------------
#define TK_INSERT(T, v)                                   \
    do { float _v = (v);                                  \
        _Pragma("unroll")                                 \
        for (int _k = 0; _k < KTOP; _k++) {               \
            float _t = T[_k];                             \
            T[_k] = fmaxf(_t, _v);                        \
            _v = fminf(_t, _v);                           \
        }                                                 \
    } while (0)

// ---------------- exact top-32 from candidate buffer + LSE ----------------
__global__ void __launch_bounds__(256) k_select() {
    int p = blockIdx.y;
    int N = g_N[p];
    int i = blockIdx.x * 256 + threadIdx.x;
    if (i >= N) return;
    int cnt = g_cnt[p][i];
    // overflow, or underflow that isn't "all negatives collected" -> exact fallback
    if (cnt > BUFC || (cnt < KTOP && cnt < N - 1)) { g_flag[p][i] = 1; return; }
    const float* buf = g_buf[p][i];
    float T[KTOP];
    #pragma unroll
    for (int k = 0; k < KTOP; k++) T[k] = -INFINITY;
    for (int q = 0; q < cnt; q++) {
        float v = buf[q];
        if (v > T[KTOP - 1]) TK_INSERT(T, v);
    }
    float pos = g_pos[p][i];
    float m = fmaxf(pos, T[0]);
    float s = expf(pos - m);
    #pragma unroll
    for (int k = 0; k < KTOP; k++) s += expf(T[k] - m);
    g_rowloss[p][i] = m + logf(s) - pos;
}

// ---------------- exact fallback: warp-per-row recompute from Z ----------------
__global__ void __launch_bounds__(256) k_fallback() {
    int p = blockIdx.y;
    int N = g_N[p];
    int lane = threadIdx.x & 31;
    int warp = (blockIdx.x * 256 + threadIdx.x) >> 5;
    int nw = (gridDim.x * 256) >> 5;
    for (int i = warp; i < N; i += nw) {
        if (!g_flag[p][i]) continue;
        float4 zs = ((const float4*)(g_Zs[p] + (size_t)i * D))[lane];
        float T[KTOP];
        #pragma unroll
        for (int k = 0; k < KTOP; k++) T[k] = -INFINITY;
        float pos = 0.0f;
        for (int j = 0; j < N; j++) {
            float4 zw = ((const float4*)(g_Zw[p] + (size_t)j * D))[lane];
            float d = zs.x * zw.x + zs.y * zw.y + zs.z * zw.z + zs.w * zw.w;
            #pragma unroll
            for (int o = 16; o; o >>= 1) d += __shfl_xor_sync(0xffffffffu, d, o);
            d *= TAU_INV;
            if (j == i) pos = d;
            else if (d > T[KTOP - 1]) TK_INSERT(T, d);
        }
        float m = fmaxf(pos, T[0]);
        float s = expf(pos - m);
        #pragma unroll
        for (int k = 0; k < KTOP; k++) s += expf(T[k] - m);
        if (lane == 0) g_rowloss[p][i] = m + logf(s) - pos;
    }
}

// ---------------- deterministic reduction ----------------
__global__ void __launch_bounds__(1024) k_reduce() {
    __shared__ float s[1024];
    int p = blockIdx.x;
    int N = g_N[p];
    int t = threadIdx.x;
    float acc = 0.0f;
    for (int i = t; i < N; i += 1024) acc += g_rowloss[p][i];
    s[t] = acc;
    __syncthreads();
    for (int o = 512; o; o >>= 1) {
        if (t < o) s[t] += s[t + o];
        __syncthreads();
    }
    if (t == 0) g_pair[p] = (N >= 4) ? s[0] / (float)N : 0.0f;
}

__global__ void k_final(float* __restrict__ out) {
    out[0] = 0.2f * g_pair[0] + 1.0f * g_pair[1] + 1.0f * g_pair[2];
}

// ---------------- launch ----------------
extern "C" void kernel_launch(void* const* d_in, const int* in_sizes, int n_in,
                              void* d_out, int out_size) {
    const float* ev = (const float*)d_in[0];
    const float* ec = (const float*)d_in[1];
    const float* ep = (const float*)d_in[2];
    const void*  uv = d_in[3]; int nv  = in_sizes[3];
    const void*  uc = d_in[4]; int nc  = in_sizes[4];
    const void*  up = d_in[5]; int np_ = in_sizes[5];

    int nwmax = nv > nc ? nv : nc; if (np_ > nwmax) nwmax = np_;
    int nblk = (nwmax + CBS - 1) / CBS; if (nblk > CMAXB) nblk = CMAXB;

    k_detect<<<1, 64>>>((const int*)uv, nv);
    k_zero<<<64, 256>>>();
    k_build<<<(nwmax + 255) / 256, 256>>>(uc, nc, up, np_);
    // pairs: (view->cart), (cart->purchase), (view->purchase)
    k_ccount<<<dim3(nblk, 3), CBS>>>(uv, nv, uc, nc, uv, nv);
    k_cscan<<<1, 32>>>(nblk);
    k_cwrite<<<dim3(nblk, 3), CBS>>>(uv, nv, uc, nc, uv, nv);
    k_gather<<<dim3(NMAX / 8, 3), 256>>>(ev, ec, ep);
    k_gemm<<<296, 256>>>();
    k_select<<<dim3(NMAX / 256, 3), 256>>>();
    k_fallback<<<dim3(32, 3), 256>>>();
    k_reduce<<<3, 1024>>>();
    k_final<<<1, 1>>>((float*)d_out);
}

// round 9
// speedup vs baseline: 2.8650x; 1.6258x over previous
#include <cuda_runtime.h>
#include <cuda_bf16.h>
#include <math.h>

// ---------------- problem constants ----------------
#define D        128
#define NMAX     4096          // max overlap (actual ~2800)
#define KTOP     32
#define TAU_INV  10.0f
#define BITW     4096          // 4096*32 bits >= U=100000
#define GT       128           // gemm tile (M=N=128)
#define BUFC     160           // per-row candidate buffer capacity
#define C0       80.0f         // target expected candidates per row
#define CBS      256           // compaction block size
#define CMAXB    128           // max compaction blocks per pair

// smem tile geometry: 128 rows x 128 bf16, rows padded to 272B (conflict-free ldmatrix)
#define ROWB     272
#define TILEB    (128 * ROWB)          // 34816 B per tile
#define SMEMB    (2 * TILEB)           // 69632 B total

// ---------------- device scratch ----------------
__device__ __nv_bfloat16 g_Zwb[3][(size_t)NMAX * D];  // weak  (j / N dim); rows>=N stay 0
__device__ __nv_bfloat16 g_Zsb[3][(size_t)NMAX * D];  // strong(i / M dim)
__device__ float        g_buf[3][NMAX][BUFC];
__device__ float        g_pos[3][NMAX];
__device__ int          g_cnt[3][NMAX];
__device__ int          g_flag[3][NMAX];
__device__ float        g_rowloss[3][NMAX];
__device__ float        g_pair[3];
__device__ float        g_thp[3];
__device__ unsigned int g_bitmap[2][BITW];            // 0: cart, 1: purchase
__device__ int          g_common[3][NMAX];
__device__ int          g_bcnt[3][CMAXB];
__device__ int          g_N[3];
__device__ int          g_is64;

// ---------------- small helpers ----------------
__device__ __forceinline__ unsigned smem_u32(const void* p) {
    unsigned a;
    asm("{ .reg .u64 t; cvta.to.shared.u64 t, %1; cvt.u32.u64 %0, t; }"
        : "=r"(a) : "l"(p));
    return a;
}
__device__ __forceinline__ int get_user(const void* p, int i) {
    return g_is64 ? (int)((const long long*)p)[i] : ((const int*)p)[i];
}
__device__ __forceinline__ int in_set(int bm, int v) {
    unsigned uv = (unsigned)v;
    return (uv < BITW * 32u) && ((g_bitmap[bm][uv >> 5] >> (uv & 31)) & 1u);
}

// ---------------- zero scratch + int64 detect (fused) ----------------
__global__ void k_zero(const int* __restrict__ u, int n) {
    int t = blockIdx.x * blockDim.x + threadIdx.x;
    int stride = gridDim.x * blockDim.x;
    for (int i = t; i < 2 * BITW; i += stride) ((unsigned*)g_bitmap)[i] = 0u;
    for (int i = t; i < 3 * NMAX; i += stride) { ((int*)g_cnt)[i] = 0; ((int*)g_flag)[i] = 0; }
    if (t < 3) g_N[t] = 0;
    if (blockIdx.x == 0) {
        __shared__ int nz;
        if (threadIdx.x == 0) nz = 0;
        __syncthreads();
        int limit = n < 128 ? n : 128;
        for (int i = 1 + 2 * (int)threadIdx.x; i < limit; i += 2 * (int)blockDim.x)
            if (u[i] != 0) atomicAdd(&nz, 1);
        __syncthreads();
        if (threadIdx.x == 0) g_is64 = (nz == 0) ? 1 : 0;
    }
}

__global__ void k_build(const void* __restrict__ uc, int nc,
                        const void* __restrict__ up, int npv) {
    int i = blockIdx.x * blockDim.x + threadIdx.x;
    if (i < nc) {
        unsigned v = (unsigned)get_user(uc, i);
        if (v < BITW * 32u) atomicOr(&g_bitmap[0][v >> 5], 1u << (v & 31));
    }
    if (i < npv) {
        unsigned v = (unsigned)get_user(up, i);
        if (v < BITW * 32u) atomicOr(&g_bitmap[1][v >> 5], 1u << (v & 31));
    }
}

// ---------------- compaction ----------------
__device__ __forceinline__ void pair_src(int p, const void* uw0, int n0,
                                         const void* uw1, int n1,
                                         const void* uw2, int n2,
                                         const void*& uw, int& nw, int& bm) {
    uw = p == 0 ? uw0 : (p == 1 ? uw1 : uw2);
    nw = p == 0 ? n0  : (p == 1 ? n1  : n2);
    bm = p == 0 ? 0 : 1;
}

__global__ void __launch_bounds__(CBS)
k_ccount(const void* uw0, int n0, const void* uw1, int n1,
         const void* uw2, int n2) {
    __shared__ int ws[CBS / 32];
    int p = blockIdx.y;
    const void* uw; int nw, bm;
    pair_src(p, uw0, n0, uw1, n1, uw2, n2, uw, nw, bm);
    int i = blockIdx.x * CBS + threadIdx.x;
    int flag = (i < nw) ? in_set(bm, get_user(uw, i)) : 0;
    unsigned b = __ballot_sync(0xffffffffu, flag);
    int lane = threadIdx.x & 31, wid = threadIdx.x >> 5;
    if (lane == 0) ws[wid] = __popc(b);
    __syncthreads();
    if (threadIdx.x == 0) {
        int s = 0;
        #pragma unroll
        for (int w = 0; w < CBS / 32; w++) s += ws[w];
        g_bcnt[p][blockIdx.x] = s;
    }
}

__global__ void __launch_bounds__(CBS)
k_cwrite(const void* uw0, int n0, const void* uw1, int n1,
         const void* uw2, int n2, int nblk) {
    __shared__ int ws[CBS / 32];
    __shared__ int wo[CBS / 32];
    __shared__ int blkbase;
    int p = blockIdx.y;
    const void* uw; int nw, bm;
    pair_src(p, uw0, n0, uw1, n1, uw2, n2, uw, nw, bm);
    int i = blockIdx.x * CBS + threadIdx.x;
    int v = 0, flag = 0;
    if (i < nw) { v = get_user(uw, i); flag = in_set(bm, v); }
    unsigned b = __ballot_sync(0xffffffffu, flag);
    int lane = threadIdx.x & 31, wid = threadIdx.x >> 5;
    int wp = __popc(b & ((1u << lane) - 1));
    if (lane == 0) ws[wid] = __popc(b);
    if (threadIdx.x == 0) {
        int acc = 0;
        for (int q = 0; q < (int)blockIdx.x; q++) acc += g_bcnt[p][q];
        blkbase = acc;
        if (blockIdx.x == 0) {
            int tot = 0;
            for (int q = 0; q < nblk; q++) tot += g_bcnt[p][q];
            int N = tot > NMAX ? NMAX : tot;
            g_N[p] = N;
            float th = -1e30f;
            if (N > BUFC) {
                float sigma = TAU_INV / sqrtf((float)D);
                th = sigma * 1.4142136f * erfinvf(1.0f - (2.0f * C0) / (float)N);
            }
            g_thp[p] = th;
        }
    }
    __syncthreads();
    if (threadIdx.x == 0) {
        int s = 0;
        #pragma unroll
        for (int w = 0; w < CBS / 32; w++) { wo[w] = s; s += ws[w]; }
    }
    __syncthreads();
    int pos = blkbase + wo[wid] + wp;
    if (flag && pos < NMAX) g_common[p][pos] = v;
}

// ---------------- gather + L2 normalize -> bf16 ----------------
__global__ void __launch_bounds__(256)
k_gather(const float* ev, const float* ec, const float* ep) {
    int p = blockIdx.y;
    const float* ew = p == 0 ? ev : (p == 1 ? ec : ev);
    const float* es = p == 0 ? ec : ep;
    int N = g_N[p];
    int lane = threadIdx.x & 31;
    int row  = blockIdx.x * 8 + (threadIdx.x >> 5);
    if (row >= N) return;
    int u = g_common[p][row];
    {
        float4 a = ((const float4*)(ew + (size_t)u * D))[lane];
        float ss = a.x * a.x + a.y * a.y + a.z * a.z + a.w * a.w;
        #pragma unroll
        for (int o = 16; o; o >>= 1) ss += __shfl_xor_sync(0xffffffffu, ss, o);
        float inv = 1.0f / fmaxf(sqrtf(ss), 1e-12f);
        __nv_bfloat162 lo = __floats2bfloat162_rn(a.x * inv, a.y * inv);
        __nv_bfloat162 hi = __floats2bfloat162_rn(a.z * inv, a.w * inv);
        ((uint2*)(g_Zwb[p] + (size_t)row * D))[lane] =
            make_uint2(*(unsigned*)&lo, *(unsigned*)&hi);
    }
    {
        float4 a = ((const float4*)(es + (size_t)u * D))[lane];
        float ss = a.x * a.x + a.y * a.y + a.z * a.z + a.w * a.w;
        #pragma unroll
        for (int o = 16; o; o >>= 1) ss += __shfl_xor_sync(0xffffffffu, ss, o);
        float inv = 1.0f / fmaxf(sqrtf(ss), 1e-12f);
        __nv_bfloat162 lo = __floats2bfloat162_rn(a.x * inv, a.y * inv);
        __nv_bfloat162 hi = __floats2bfloat162_rn(a.z * inv, a.w * inv);
        ((uint2*)(g_Zsb[p] + (size_t)row * D))[lane] =
            make_uint2(*(unsigned*)&lo, *(unsigned*)&hi);
    }
}

// ---------------- mma.sync helpers (base PTX ISA, compiles on compute_103) ----
__device__ __forceinline__ void ldmx4(unsigned& r0, unsigned& r1,
                                      unsigned& r2, unsigned& r3, unsigned a) {
    asm volatile("ldmatrix.sync.aligned.m8n8.x4.shared.b16 {%0,%1,%2,%3}, [%4];"
                 : "=r"(r0), "=r"(r1), "=r"(r2), "=r"(r3) : "r"(a));
}
__device__ __forceinline__ void mma_bf16(float* c, const unsigned* a,
                                         unsigned b0, unsigned b1) {
    asm volatile(
        "mma.sync.aligned.m16n8k16.row.col.f32.bf16.bf16.f32 "
        "{%0,%1,%2,%3}, {%4,%5,%6,%7}, {%8,%9}, {%0,%1,%2,%3};"
        : "+f"(c[0]), "+f"(c[1]), "+f"(c[2]), "+f"(c[3])
        : "r"(a[0]), "r"(a[1]), "r"(a[2]), "r"(a[3]), "r"(b0), "r"(b1));
}

// ---------------- HMMA GEMM (128x128x128 tile) + fused threshold epilogue ----
// sim[i][j]*10 = 10*dot(Zs[i0+m], Zw[j0+n]).  8 warps = 4(m) x 2(n); warp tile
// 32x64; m16n8k16 frags: 2 m-frags x 8 n-frags, 8 k-steps.
__global__ void __launch_bounds__(256) k_gemm_mma() {
    extern __shared__ __align__(16) char smem[];
    char* smA = smem;
    char* smB = smem + TILEB;
    unsigned sA = smem_u32(smA);
    unsigned sB = sA + TILEB;

    int tid = threadIdx.x;
    int lane = tid & 31, wid = tid >> 5;
    int warp_m = wid >> 1;          // 0..3  -> m offset 32*warp_m
    int warp_n = wid & 1;           // 0..1  -> n offset 64*warp_n

    int nb0 = (g_N[0] + GT - 1) >> 7, nt0 = nb0 * nb0;
    int nb1 = (g_N[1] + GT - 1) >> 7, nt1 = nb1 * nb1;
    int nb2 = (g_N[2] + GT - 1) >> 7, nt2 = nb2 * nb2;
    int total = nt0 + nt1 + nt2;

    // ldmatrix source addresses (fixed per thread, +k-step offset)
    // A: groups g=lane>>3: m = (g&1)*8 + (lane&7), k = (g>>1)*8
    int a_row = ((lane >> 3) & 1) * 8 + (lane & 7);
    int a_kof = (lane >> 4) * 8;
    // B: n = ((lane>>4)<<3) + (lane&7), k = ((lane>>3)&1)*8
    int b_row = ((lane >> 4) << 3) + (lane & 7);
    int b_kof = ((lane >> 3) & 1) * 8;

    for (int t = blockIdx.x; t < total; t += gridDim.x) {
        int p, tt, nb;
        if (t < nt0)            { p = 0; tt = t;             nb = nb0; }
        else if (t < nt0 + nt1) { p = 1; tt = t - nt0;       nb = nb1; }
        else                    { p = 2; tt = t - nt0 - nt1; nb = nb2; }
        int N = g_N[p];
        int i0 = (tt / nb) << 7;     // strong rows (m)
        int j0 = (tt % nb) << 7;     // weak rows (n)
        const __nv_bfloat16* Zs = g_Zsb[p];
        const __nv_bfloat16* Zw = g_Zwb[p];

        // ---- load tiles: 128 rows x 256B, padded rows of 272B ----
        #pragma unroll
        for (int q = tid; q < 2048; q += 256) {
            int row = q >> 4, ch = q & 15;
            *(uint4*)(smA + row * ROWB + ch * 16) =
                *(const uint4*)(Zs + (size_t)(i0 + row) * D + ch * 8);
            *(uint4*)(smB + row * ROWB + ch * 16) =
                *(const uint4*)(Zw + (size_t)(j0 + row) * D + ch * 8);
        }
        __syncthreads();

        float c[2][8][4];
        #pragma unroll
        for (int mf = 0; mf < 2; mf++)
            #pragma unroll
            for (int nf = 0; nf < 8; nf++)
                #pragma unroll
                for (int r = 0; r < 4; r++) c[mf][nf][r] = 0.0f;

        unsigned aBase = sA + (warp_m * 32 + a_row) * ROWB + a_kof * 2;
        unsigned bBase = sB + (warp_n * 64 + b_row) * ROWB + b_kof * 2;

        #pragma unroll
        for (int ks = 0; ks < 8; ks++) {
            unsigned kb = ks * 32;               // 16 bf16 = 32 bytes
            unsigned a0[4], a1[4];
            ldmx4(a0[0], a0[1], a0[2], a0[3], aBase + kb);
            ldmx4(a1[0], a1[1], a1[2], a1[3], aBase + 16 * ROWB + kb);
            unsigned bf[8][2];
            #pragma unroll
            for (int bg = 0; bg < 4; bg++) {
                unsigned r0, r1, r2, r3;
                ldmx4(r0, r1, r2, r3, bBase + bg * 16 * ROWB + kb);
                bf[bg * 2 + 0][0] = r0; bf[bg * 2 + 0][1] = r1;
                bf[bg * 2 + 1][0] = r2; bf[bg * 2 + 1][1] = r3;
            }
            #pragma unroll
            for (int nf = 0; nf < 8; nf++) {
                mma_bf16(c[0][nf], a0, bf[nf][0], bf[nf][1]);
                mma_bf16(c[1][nf], a1, bf[nf][0], bf[nf][1]);
            }
        }
        __syncthreads();     // smem consumed; safe to overwrite next iter

        // ---- fused epilogue: threshold-collect + diagonal capture ----
        float th = g_thp[p];
        int mrow = lane >> 2;           // 0..7
        int ncol = (lane & 3) * 2;      // 0,2,4,6
        #pragma unroll
        for (int mf = 0; mf < 2; mf++) {
            #pragma unroll
            for (int nf = 0; nf < 8; nf++) {
                #pragma unroll
                for (int r = 0; r < 4; r++) {
                    int ig = i0 + warp_m * 32 + mf * 16 + mrow + ((r >> 1) << 3);
                    int jg = j0 + warp_n * 64 + nf * 8 + ncol + (r & 1);
                    if (ig >= N || jg >= N) continue;
                    float v = c[mf][nf][r] * TAU_INV;
                    if (jg == ig) g_pos[p][ig] = v;
                    else if (v >= th) {
                        int q = atomicAdd(&g_cnt[p][ig], 1);
                        if (q < BUFC) g_buf[p][ig][q] = v; else g_flag[p][ig] = 1;
                    }
                }
            }
        }
    }
}

// ---------------- sorted-descending register insert ----------------
#define TK_INSERT(T, v)                                   \
    do { float _v = (v);                                  \
        _Pragma("unroll")                                 \
        for (int _k = 0; _k < KTOP; _k++) {               \
            float _t = T[_k];                             \
            T[_k] = fmaxf(_t, _v);                        \
            _v = fminf(_t, _v);                           \
        }                                                 \
    } while (0)

// ---------------- exact top-32 from candidate buffer + LSE ----------------
__global__ void __launch_bounds__(256) k_select() {
    int p = blockIdx.y;
    int N = g_N[p];
    int i = blockIdx.x * 256 + threadIdx.x;
    if (i >= N) return;
    int cnt = g_cnt[p][i];
    if (cnt > BUFC || (cnt < KTOP && cnt < N - 1)) { g_flag[p][i] = 1; return; }
    const float* buf = g_buf[p][i];
    float T[KTOP];
    #pragma unroll
    for (int k = 0; k < KTOP; k++) T[k] = -INFINITY;
    for (int q = 0; q < cnt; q++) {
        float v = buf[q];
        if (v > T[KTOP - 1]) TK_INSERT(T, v);
    }
    float pos = g_pos[p][i];
    float m = fmaxf(pos, T[0]);
    float s = expf(pos - m);
    #pragma unroll
    for (int k = 0; k < KTOP; k++) s += expf(T[k] - m);
    g_rowloss[p][i] = m + logf(s) - pos;
}

// ---------------- exact fallback: warp-per-row recompute (bf16) ----------------
__global__ void __launch_bounds__(256) k_fallback() {
    int p = blockIdx.y;
    int N = g_N[p];
    int lane = threadIdx.x & 31;
    int warp = (blockIdx.x * 256 + threadIdx.x) >> 5;
    int nw = (gridDim.x * 256) >> 5;
    for (int i = warp; i < N; i += nw) {
        if (!g_flag[p][i]) continue;
        uint2 rs = ((const uint2*)(g_Zsb[p] + (size_t)i * D))[lane];
        __nv_bfloat162 s0 = *(__nv_bfloat162*)&rs.x, s1 = *(__nv_bfloat162*)&rs.y;
        float a0 = __low2float(s0), a1 = __high2float(s0);
        float a2 = __low2float(s1), a3 = __high2float(s1);
        float T[KTOP];
        #pragma unroll
        for (int k = 0; k < KTOP; k++) T[k] = -INFINITY;
        float pos = 0.0f;
        for (int j = 0; j < N; j++) {
            uint2 rw = ((const uint2*)(g_Zwb[p] + (size_t)j * D))[lane];
            __nv_bfloat162 w0 = *(__nv_bfloat162*)&rw.x, w1 = *(__nv_bfloat162*)&rw.y;
            float d = a0 * __low2float(w0) + a1 * __high2float(w0)
                    + a2 * __low2float(w1) + a3 * __high2float(w1);
            #pragma unroll
            for (int o = 16; o; o >>= 1) d += __shfl_xor_sync(0xffffffffu, d, o);
            d *= TAU_INV;
            if (j == i) pos = d;
            else if (d > T[KTOP - 1]) TK_INSERT(T, d);
        }
        float m = fmaxf(pos, T[0]);
        float s = expf(pos - m);
        #pragma unroll
        for (int k = 0; k < KTOP; k++) s += expf(T[k] - m);
        if (lane == 0) g_rowloss[p][i] = m + logf(s) - pos;
    }
}

// ---------------- deterministic reduction ----------------
__global__ void __launch_bounds__(1024) k_reduce() {
    __shared__ float s[1024];
    int p = blockIdx.x;
    int N = g_N[p];
    int t = threadIdx.x;
    float acc = 0.0f;
    for (int i = t; i < N; i += 1024) acc += g_rowloss[p][i];
    s[t] = acc;
    __syncthreads();
    for (int o = 512; o; o >>= 1) {
        if (t < o) s[t] += s[t + o];
        __syncthreads();
    }
    if (t == 0) g_pair[p] = (N >= 4) ? s[0] / (float)N : 0.0f;
}

__global__ void k_final(float* __restrict__ out) {
    out[0] = 0.2f * g_pair[0] + 1.0f * g_pair[1] + 1.0f * g_pair[2];
}

// ---------------- launch ----------------
extern "C" void kernel_launch(void* const* d_in, const int* in_sizes, int n_in,
                              void* d_out, int out_size) {
    const float* ev = (const float*)d_in[0];
    const float* ec = (const float*)d_in[1];
    const float* ep = (const float*)d_in[2];
    const void*  uv = d_in[3]; int nv  = in_sizes[3];
    const void*  uc = d_in[4]; int nc  = in_sizes[4];
    const void*  up = d_in[5]; int np_ = in_sizes[5];

    int nwmax = nv > nc ? nv : nc; if (np_ > nwmax) nwmax = np_;
    int nblk = (nwmax + CBS - 1) / CBS; if (nblk > CMAXB) nblk = CMAXB;

    static int attr_done = 0;
    if (!attr_done) {
        cudaFuncSetAttribute(k_gemm_mma,
                             cudaFuncAttributeMaxDynamicSharedMemorySize, SMEMB);
        attr_done = 1;
    }

    k_zero<<<64, 256>>>((const int*)uv, nv);
    k_build<<<(nwmax + 255) / 256, 256>>>(uc, nc, up, np_);
    // pairs: (view->cart), (cart->purchase), (view->purchase)
    k_ccount<<<dim3(nblk, 3), CBS>>>(uv, nv, uc, nc, uv, nv);
    k_cwrite<<<dim3(nblk, 3), CBS>>>(uv, nv, uc, nc, uv, nv, nblk);
    k_gather<<<dim3(NMAX / 8, 3), 256>>>(ev, ec, ep);
    k_gemm_mma<<<296, 256, SMEMB>>>();
    k_select<<<dim3(NMAX / 256, 3), 256>>>();
    k_fallback<<<dim3(32, 3), 256>>>();
    k_reduce<<<3, 1024>>>();
    k_final<<<1, 1>>>((float*)d_out);
}

// round 10
// speedup vs baseline: 2.9704x; 1.0368x over previous
#include <cuda_runtime.h>
#include <cuda_bf16.h>
#include <math.h>

// ---------------- problem constants ----------------
#define D        128
#define NMAX     4096          // max overlap (actual ~2800)
#define KTOP     32
#define TAU_INV  10.0f
#define BITW     4096          // 4096*32 bits >= U=100000
#define GT       128           // gemm tile (M=N=128)
#define BUFC     160           // per-row candidate buffer capacity
#define C0       80.0f         // target expected candidates per row
#define CBS      256           // compaction block size
#define CMAXB    128           // max compaction blocks per pair

// smem tile geometry: 128 rows x 128 bf16, rows padded to 272B (conflict-free ldmatrix)
#define ROWB     272
#define TILEB    (128 * ROWB)          // 34816 B per tile
#define SMEMB    (2 * TILEB)           // 69632 B total

// ---------------- device scratch ----------------
__device__ __nv_bfloat16 g_Zwb[3][(size_t)NMAX * D];  // weak  (j / N dim); rows>=N stay 0
__device__ __nv_bfloat16 g_Zsb[3][(size_t)NMAX * D];  // strong(i / M dim)
__device__ float        g_buf[3][NMAX][BUFC];
__device__ float        g_pos[3][NMAX];
__device__ int          g_cnt[3][NMAX];
__device__ int          g_flag[3][NMAX];
__device__ float        g_rowloss[3][NMAX];
__device__ float        g_thp[3];
__device__ unsigned int g_bitmap[2][BITW];            // 0: cart, 1: purchase
__device__ int          g_common[3][NMAX];
__device__ int          g_bcnt[3][CMAXB];
__device__ int          g_N[3];
__device__ int          g_is64;

// ---------------- small helpers ----------------
__device__ __forceinline__ unsigned smem_u32(const void* p) {
    unsigned a;
    asm("{ .reg .u64 t; cvta.to.shared.u64 t, %1; cvt.u32.u64 %0, t; }"
        : "=r"(a) : "l"(p));
    return a;
}
__device__ __forceinline__ int get_user(const void* p, int i) {
    return g_is64 ? (int)((const long long*)p)[i] : ((const int*)p)[i];
}
__device__ __forceinline__ int in_set(int bm, int v) {
    unsigned uv = (unsigned)v;
    return (uv < BITW * 32u) && ((g_bitmap[bm][uv >> 5] >> (uv & 31)) & 1u);
}

// ---------------- zero scratch + int64 detect (fused) ----------------
__global__ void k_zero(const int* __restrict__ u, int n) {
    int t = blockIdx.x * blockDim.x + threadIdx.x;
    int stride = gridDim.x * blockDim.x;
    for (int i = t; i < 2 * BITW; i += stride) ((unsigned*)g_bitmap)[i] = 0u;
    for (int i = t; i < 3 * NMAX; i += stride) { ((int*)g_cnt)[i] = 0; ((int*)g_flag)[i] = 0; }
    if (t < 3) g_N[t] = 0;
    if (blockIdx.x == 0) {
        __shared__ int nz;
        if (threadIdx.x == 0) nz = 0;
        __syncthreads();
        int limit = n < 128 ? n : 128;
        for (int i = 1 + 2 * (int)threadIdx.x; i < limit; i += 2 * (int)blockDim.x)
            if (u[i] != 0) atomicAdd(&nz, 1);
        __syncthreads();
        if (threadIdx.x == 0) g_is64 = (nz == 0) ? 1 : 0;
    }
}

__global__ void k_build(const void* __restrict__ uc, int nc,
                        const void* __restrict__ up, int npv) {
    int i = blockIdx.x * blockDim.x + threadIdx.x;
    if (i < nc) {
        unsigned v = (unsigned)get_user(uc, i);
        if (v < BITW * 32u) atomicOr(&g_bitmap[0][v >> 5], 1u << (v & 31));
    }
    if (i < npv) {
        unsigned v = (unsigned)get_user(up, i);
        if (v < BITW * 32u) atomicOr(&g_bitmap[1][v >> 5], 1u << (v & 31));
    }
}

// ---------------- compaction ----------------
__device__ __forceinline__ void pair_src(int p, const void* uw0, int n0,
                                         const void* uw1, int n1,
                                         const void* uw2, int n2,
                                         const void*& uw, int& nw, int& bm) {
    uw = p == 0 ? uw0 : (p == 1 ? uw1 : uw2);
    nw = p == 0 ? n0  : (p == 1 ? n1  : n2);
    bm = p == 0 ? 0 : 1;
}

__global__ void __launch_bounds__(CBS)
k_ccount(const void* uw0, int n0, const void* uw1, int n1,
         const void* uw2, int n2) {
    __shared__ int ws[CBS / 32];
    int p = blockIdx.y;
    const void* uw; int nw, bm;
    pair_src(p, uw0, n0, uw1, n1, uw2, n2, uw, nw, bm);
    int i = blockIdx.x * CBS + threadIdx.x;
    int flag = (i < nw) ? in_set(bm, get_user(uw, i)) : 0;
    unsigned b = __ballot_sync(0xffffffffu, flag);
    int lane = threadIdx.x & 31, wid = threadIdx.x >> 5;
    if (lane == 0) ws[wid] = __popc(b);
    __syncthreads();
    if (threadIdx.x == 0) {
        int s = 0;
        #pragma unroll
        for (int w = 0; w < CBS / 32; w++) s += ws[w];
        g_bcnt[p][blockIdx.x] = s;
    }
}

// write + PARALLEL prefix of block counts; block 0 also sets g_N / threshold
__global__ void __launch_bounds__(CBS)
k_cwrite(const void* uw0, int n0, const void* uw1, int n1,
         const void* uw2, int n2, int nblk) {
    __shared__ int ws[CBS / 32];
    __shared__ int wo[CBS / 32];
    __shared__ int red[CBS];
    __shared__ int blkbase;
    int p = blockIdx.y;
    int tid = threadIdx.x;
    const void* uw; int nw, bm;
    pair_src(p, uw0, n0, uw1, n1, uw2, n2, uw, nw, bm);
    int i = blockIdx.x * CBS + tid;
    int v = 0, flag = 0;
    if (i < nw) { v = get_user(uw, i); flag = in_set(bm, v); }
    unsigned b = __ballot_sync(0xffffffffu, flag);
    int lane = tid & 31, wid = tid >> 5;
    int wp = __popc(b & ((1u << lane) - 1));
    if (lane == 0) ws[wid] = __popc(b);

    // parallel load of block counts: base (q < blockIdx.x) and total
    int baseacc = 0, totacc = 0;
    for (int q = tid; q < nblk; q += CBS) {
        int c = g_bcnt[p][q];
        totacc += c;
        if (q < (int)blockIdx.x) baseacc += c;
    }
    red[tid] = baseacc;
    __syncthreads();
    for (int o = CBS / 2; o; o >>= 1) {
        if (tid < o) red[tid] += red[tid + o];
        __syncthreads();
    }
    if (tid == 0) blkbase = red[0];
    __syncthreads();
    red[tid] = totacc;
    __syncthreads();
    for (int o = CBS / 2; o; o >>= 1) {
        if (tid < o) red[tid] += red[tid + o];
        __syncthreads();
    }
    if (tid == 0 && blockIdx.x == 0) {
        int tot = red[0];
        int N = tot > NMAX ? NMAX : tot;
        g_N[p] = N;
        float th = -1e30f;
        if (N > BUFC) {
            float sigma = TAU_INV / sqrtf((float)D);
            th = sigma * 1.4142136f * erfinvf(1.0f - (2.0f * C0) / (float)N);
        }
        g_thp[p] = th;
    }
    if (tid == 0) {
        int s = 0;
        #pragma unroll
        for (int w = 0; w < CBS / 32; w++) { wo[w] = s; s += ws[w]; }
    }
    __syncthreads();
    int pos = blkbase + wo[wid] + wp;
    if (flag && pos < NMAX) g_common[p][pos] = v;
}

// ---------------- gather + L2 normalize -> bf16 ----------------
__global__ void __launch_bounds__(256)
k_gather(const float* ev, const float* ec, const float* ep) {
    int p = blockIdx.y;
    const float* ew = p == 0 ? ev : (p == 1 ? ec : ev);
    const float* es = p == 0 ? ec : ep;
    int N = g_N[p];
    int lane = threadIdx.x & 31;
    int row  = blockIdx.x * 8 + (threadIdx.x >> 5);
    if (row >= N) return;
    int u = g_common[p][row];
    {
        float4 a = ((const float4*)(ew + (size_t)u * D))[lane];
        float ss = a.x * a.x + a.y * a.y + a.z * a.z + a.w * a.w;
        #pragma unroll
        for (int o = 16; o; o >>= 1) ss += __shfl_xor_sync(0xffffffffu, ss, o);
        float inv = 1.0f / fmaxf(sqrtf(ss), 1e-12f);
        __nv_bfloat162 lo = __floats2bfloat162_rn(a.x * inv, a.y * inv);
        __nv_bfloat162 hi = __floats2bfloat162_rn(a.z * inv, a.w * inv);
        ((uint2*)(g_Zwb[p] + (size_t)row * D))[lane] =
            make_uint2(*(unsigned*)&lo, *(unsigned*)&hi);
    }
    {
        float4 a = ((const float4*)(es + (size_t)u * D))[lane];
        float ss = a.x * a.x + a.y * a.y + a.z * a.z + a.w * a.w;
        #pragma unroll
        for (int o = 16; o; o >>= 1) ss += __shfl_xor_sync(0xffffffffu, ss, o);
        float inv = 1.0f / fmaxf(sqrtf(ss), 1e-12f);
        __nv_bfloat162 lo = __floats2bfloat162_rn(a.x * inv, a.y * inv);
        __nv_bfloat162 hi = __floats2bfloat162_rn(a.z * inv, a.w * inv);
        ((uint2*)(g_Zsb[p] + (size_t)row * D))[lane] =
            make_uint2(*(unsigned*)&lo, *(unsigned*)&hi);
    }
}

// ---------------- mma.sync helpers (base PTX ISA) ----------------
__device__ __forceinline__ void ldmx4(unsigned& r0, unsigned& r1,
                                      unsigned& r2, unsigned& r3, unsigned a) {
    asm volatile("ldmatrix.sync.aligned.m8n8.x4.shared.b16 {%0,%1,%2,%3}, [%4];"
                 : "=r"(r0), "=r"(r1), "=r"(r2), "=r"(r3) : "r"(a));
}
__device__ __forceinline__ void mma_bf16(float* c, const unsigned* a,
                                         unsigned b0, unsigned b1) {
    asm volatile(
        "mma.sync.aligned.m16n8k16.row.col.f32.bf16.bf16.f32 "
        "{%0,%1,%2,%3}, {%4,%5,%6,%7}, {%8,%9}, {%0,%1,%2,%3};"
        : "+f"(c[0]), "+f"(c[1]), "+f"(c[2]), "+f"(c[3])
        : "r"(a[0]), "r"(a[1]), "r"(a[2]), "r"(a[3]), "r"(b0), "r"(b1));
}

// ---------------- HMMA GEMM (128x128x128 tile) + fused threshold epilogue ----
__global__ void __launch_bounds__(256) k_gemm_mma() {
    extern __shared__ __align__(16) char smem[];
    char* smA = smem;
    char* smB = smem + TILEB;
    unsigned sA = smem_u32(smA);
    unsigned sB = sA + TILEB;

    int tid = threadIdx.x;
    int lane = tid & 31, wid = tid >> 5;
    int warp_m = wid >> 1;          // 0..3  -> m offset 32*warp_m
    int warp_n = wid & 1;           // 0..1  -> n offset 64*warp_n

    int nb0 = (g_N[0] + GT - 1) >> 7, nt0 = nb0 * nb0;
    int nb1 = (g_N[1] + GT - 1) >> 7, nt1 = nb1 * nb1;
    int nb2 = (g_N[2] + GT - 1) >> 7, nt2 = nb2 * nb2;
    int total = nt0 + nt1 + nt2;

    int a_row = ((lane >> 3) & 1) * 8 + (lane & 7);
    int a_kof = (lane >> 4) * 8;
    int b_row = ((lane >> 4) << 3) + (lane & 7);
    int b_kof = ((lane >> 3) & 1) * 8;

    for (int t = blockIdx.x; t < total; t += gridDim.x) {
        int p, tt, nb;
        if (t < nt0)            { p = 0; tt = t;             nb = nb0; }
        else if (t < nt0 + nt1) { p = 1; tt = t - nt0;       nb = nb1; }
        else                    { p = 2; tt = t - nt0 - nt1; nb = nb2; }
        int N = g_N[p];
        int i0 = (tt / nb) << 7;     // strong rows (m)
        int j0 = (tt % nb) << 7;     // weak rows (n)
        const __nv_bfloat16* Zs = g_Zsb[p];
        const __nv_bfloat16* Zw = g_Zwb[p];

        #pragma unroll
        for (int q = tid; q < 2048; q += 256) {
            int row = q >> 4, ch = q & 15;
            *(uint4*)(smA + row * ROWB + ch * 16) =
                *(const uint4*)(Zs + (size_t)(i0 + row) * D + ch * 8);
            *(uint4*)(smB + row * ROWB + ch * 16) =
                *(const uint4*)(Zw + (size_t)(j0 + row) * D + ch * 8);
        }
        __syncthreads();

        float c[2][8][4];
        #pragma unroll
        for (int mf = 0; mf < 2; mf++)
            #pragma unroll
            for (int nf = 0; nf < 8; nf++)
                #pragma unroll
                for (int r = 0; r < 4; r++) c[mf][nf][r] = 0.0f;

        unsigned aBase = sA + (warp_m * 32 + a_row) * ROWB + a_kof * 2;
        unsigned bBase = sB + (warp_n * 64 + b_row) * ROWB + b_kof * 2;

        #pragma unroll
        for (int ks = 0; ks < 8; ks++) {
            unsigned kb = ks * 32;
            unsigned a0[4], a1[4];
            ldmx4(a0[0], a0[1], a0[2], a0[3], aBase + kb);
            ldmx4(a1[0], a1[1], a1[2], a1[3], aBase + 16 * ROWB + kb);
            unsigned bf[8][2];
            #pragma unroll
            for (int bg = 0; bg < 4; bg++) {
                unsigned r0, r1, r2, r3;
                ldmx4(r0, r1, r2, r3, bBase + bg * 16 * ROWB + kb);
                bf[bg * 2 + 0][0] = r0; bf[bg * 2 + 0][1] = r1;
                bf[bg * 2 + 1][0] = r2; bf[bg * 2 + 1][1] = r3;
            }
            #pragma unroll
            for (int nf = 0; nf < 8; nf++) {
                mma_bf16(c[0][nf], a0, bf[nf][0], bf[nf][1]);
                mma_bf16(c[1][nf], a1, bf[nf][0], bf[nf][1]);
            }
        }
        __syncthreads();

        float th = g_thp[p];
        int mrow = lane >> 2;
        int ncol = (lane & 3) * 2;
        #pragma unroll
        for (int mf = 0; mf < 2; mf++) {
            #pragma unroll
            for (int nf = 0; nf < 8; nf++) {
                #pragma unroll
                for (int r = 0; r < 4; r++) {
                    int ig = i0 + warp_m * 32 + mf * 16 + mrow + ((r >> 1) << 3);
                    int jg = j0 + warp_n * 64 + nf * 8 + ncol + (r & 1);
                    if (ig >= N || jg >= N) continue;
                    float v = c[mf][nf][r] * TAU_INV;
                    if (jg == ig) g_pos[p][ig] = v;
                    else if (v >= th) {
                        int q = atomicAdd(&g_cnt[p][ig], 1);
                        if (q < BUFC) g_buf[p][ig][q] = v; else g_flag[p][ig] = 1;
                    }
                }
            }
        }
    }
}

// ---------------- sorted-descending register insert ----------------
#define TK_INSERT(T, v)                                   \
    do { float _v = (v);                                  \
        _Pragma("unroll")                                 \
        for (int _k = 0; _k < KTOP; _k++) {               \
            float _t = T[_k];                             \
            T[_k] = fmaxf(_t, _v);                        \
            _v = fminf(_t, _v);                           \
        }                                                 \
    } while (0)

// ---------- select (thread/row) + inline exact fallback (warp/row) ----------
__global__ void __launch_bounds__(256) k_select() {
    __shared__ int flist[256];
    __shared__ int fcnt;
    int p = blockIdx.y;
    int N = g_N[p];
    int tid = threadIdx.x;
    int i = blockIdx.x * 256 + tid;
    if (tid == 0) fcnt = 0;
    __syncthreads();

    if (i < N) {
        int cnt = g_cnt[p][i];
        bool bad = g_flag[p][i] || cnt > BUFC || (cnt < KTOP && cnt < N - 1);
        if (bad) {
            int q = atomicAdd(&fcnt, 1);
            flist[q] = i;
        } else {
            const float* buf = g_buf[p][i];
            float T[KTOP];
            #pragma unroll
            for (int k = 0; k < KTOP; k++) T[k] = -INFINITY;
            for (int q = 0; q < cnt; q++) {
                float v = buf[q];
                if (v > T[KTOP - 1]) TK_INSERT(T, v);
            }
            float pos = g_pos[p][i];
            float m = fmaxf(pos, T[0]);
            float s = expf(pos - m);
            #pragma unroll
            for (int k = 0; k < KTOP; k++) s += expf(T[k] - m);
            g_rowloss[p][i] = m + logf(s) - pos;
        }
    }
    __syncthreads();

    // warp-per-row exact recompute for flagged rows (expected: none)
    int nf = fcnt;
    int lane = tid & 31, wid = tid >> 5;
    for (int q = wid; q < nf; q += 8) {
        int i2 = flist[q];
        uint2 rs = ((const uint2*)(g_Zsb[p] + (size_t)i2 * D))[lane];
        __nv_bfloat162 s0 = *(__nv_bfloat162*)&rs.x, s1 = *(__nv_bfloat162*)&rs.y;
        float a0 = __low2float(s0), a1 = __high2float(s0);
        float a2 = __low2float(s1), a3 = __high2float(s1);
        float T[KTOP];
        #pragma unroll
        for (int k = 0; k < KTOP; k++) T[k] = -INFINITY;
        float pos = 0.0f;
        for (int j = 0; j < N; j++) {
            uint2 rw = ((const uint2*)(g_Zwb[p] + (size_t)j * D))[lane];
            __nv_bfloat162 w0 = *(__nv_bfloat162*)&rw.x, w1 = *(__nv_bfloat162*)&rw.y;
            float d = a0 * __low2float(w0) + a1 * __high2float(w0)
                    + a2 * __low2float(w1) + a3 * __high2float(w1);
            #pragma unroll
            for (int o = 16; o; o >>= 1) d += __shfl_xor_sync(0xffffffffu, d, o);
            d *= TAU_INV;
            if (j == i2) pos = d;
            else if (d > T[KTOP - 1]) TK_INSERT(T, d);
        }
        float m = fmaxf(pos, T[0]);
        float s = expf(pos - m);
        #pragma unroll
        for (int k = 0; k < KTOP; k++) s += expf(T[k] - m);
        if (lane == 0) g_rowloss[p][i2] = m + logf(s) - pos;
    }
}

// ---------------- deterministic reduction + final combine (one block) --------
__global__ void __launch_bounds__(1024) k_reduce(float* __restrict__ out) {
    __shared__ float s[1024];
    __shared__ float pair[3];
    int t = threadIdx.x;
    for (int p = 0; p < 3; p++) {
        int N = g_N[p];
        float acc = 0.0f;
        for (int i = t; i < N; i += 1024) acc += g_rowloss[p][i];
        s[t] = acc;
        __syncthreads();
        for (int o = 512; o; o >>= 1) {
            if (t < o) s[t] += s[t + o];
            __syncthreads();
        }
        if (t == 0) pair[p] = (N >= 4) ? s[0] / (float)N : 0.0f;
        __syncthreads();
    }
    if (t == 0) out[0] = 0.2f * pair[0] + 1.0f * pair[1] + 1.0f * pair[2];
}

// ---------------- launch ----------------
extern "C" void kernel_launch(void* const* d_in, const int* in_sizes, int n_in,
                              void* d_out, int out_size) {
    const float* ev = (const float*)d_in[0];
    const float* ec = (const float*)d_in[1];
    const float* ep = (const float*)d_in[2];
    const void*  uv = d_in[3]; int nv  = in_sizes[3];
    const void*  uc = d_in[4]; int nc  = in_sizes[4];
    const void*  up = d_in[5]; int np_ = in_sizes[5];

    int nwmax = nv > nc ? nv : nc; if (np_ > nwmax) nwmax = np_;
    int nblk = (nwmax + CBS - 1) / CBS; if (nblk > CMAXB) nblk = CMAXB;

    static int attr_done = 0;
    if (!attr_done) {
        cudaFuncSetAttribute(k_gemm_mma,
                             cudaFuncAttributeMaxDynamicSharedMemorySize, SMEMB);
        attr_done = 1;
    }

    k_zero<<<64, 256>>>((const int*)uv, nv);
    k_build<<<(nwmax + 255) / 256, 256>>>(uc, nc, up, np_);
    // pairs: (view->cart), (cart->purchase), (view->purchase)
    k_ccount<<<dim3(nblk, 3), CBS>>>(uv, nv, uc, nc, uv, nv);
    k_cwrite<<<dim3(nblk, 3), CBS>>>(uv, nv, uc, nc, uv, nv, nblk);
    k_gather<<<dim3(NMAX / 8, 3), 256>>>(ev, ec, ep);
    k_gemm_mma<<<296, 256, SMEMB>>>();
    k_select<<<dim3(NMAX / 256, 3), 256>>>();
    k_reduce<<<1, 1024>>>((float*)d_out);
}